// round 7
// baseline (speedup 1.0000x reference)
#include <cuda_runtime.h>
#include <cuda_bf16.h>
#include <cstdint>

#define DDIM   128
#define TILE_M 128
#define NTH    256
#define NWARP  8

// ---- smem layout (bytes) ----
#define A_STRIDE 272                          // bf16 row: 256 data + 16 pad
#define A_HI_OFF 0
#define A_LO_OFF (TILE_M * A_STRIDE)          // 34816
#define WLO_OFF  (2 * TILE_M * A_STRIDE)      // 69632  (W_lo bf16, padded rows)
#define ZS_OFF   (WLO_OFF + TILE_M * A_STRIDE)  // 104448
#define ZS_FSTRIDE 132
#define ZS_SZ    (TILE_M * ZS_FSTRIDE * 4)    // 67584
#define PSD_OFF  (ZS_OFF + ZS_SZ)             // 172032  [4][128] floats
#define PSN_OFF  (PSD_OFF + 4 * TILE_M * 4)
#define SC_OFF   (PSN_OFF + 4 * TILE_M * 4)
#define SMEM_TOTAL (SC_OFF + TILE_M * 4)      // 176640

__device__ __forceinline__ uint32_t s2u(const void* p) {
    return (uint32_t)__cvta_generic_to_shared(p);
}
__device__ __forceinline__ void cpa16(uint32_t dst, const void* src) {
    asm volatile("cp.async.cg.shared.global [%0], [%1], 16;" :: "r"(dst), "l"(src) : "memory");
}
__device__ __forceinline__ void cpa_commit() {
    asm volatile("cp.async.commit_group;" ::: "memory");
}
__device__ __forceinline__ void cpa_wait0() {
    asm volatile("cp.async.wait_group 0;" ::: "memory");
}
__device__ __forceinline__ void mma_bf16(float& d0, float& d1, float& d2, float& d3,
                                         uint32_t a0, uint32_t a1, uint32_t a2, uint32_t a3,
                                         uint32_t b0, uint32_t b1) {
    asm volatile("mma.sync.aligned.m16n8k16.row.col.f32.bf16.bf16.f32 "
                 "{%0,%1,%2,%3}, {%4,%5,%6,%7}, {%8,%9}, {%0,%1,%2,%3};"
                 : "+f"(d0), "+f"(d1), "+f"(d2), "+f"(d3)
                 : "r"(a0), "r"(a1), "r"(a2), "r"(a3), "r"(b0), "r"(b1));
}
__device__ __forceinline__ void ldmx4(uint32_t& r0, uint32_t& r1, uint32_t& r2, uint32_t& r3,
                                      uint32_t addr) {
    asm volatile("ldmatrix.sync.aligned.m8n8.x4.shared.b16 {%0,%1,%2,%3}, [%4];"
                 : "=r"(r0), "=r"(r1), "=r"(r2), "=r"(r3) : "r"(addr));
}
__device__ __forceinline__ void split2(float2 x, uint32_t& h, uint32_t& l) {
    __nv_bfloat16 h0 = __float2bfloat16_rn(x.x);
    __nv_bfloat16 h1 = __float2bfloat16_rn(x.y);
    __nv_bfloat16 l0 = __float2bfloat16_rn(x.x - __bfloat162float(h0));
    __nv_bfloat16 l1 = __float2bfloat16_rn(x.y - __bfloat162float(h1));
    __nv_bfloat162 hh = __halves2bfloat162(h0, h1);
    __nv_bfloat162 ll = __halves2bfloat162(l0, l1);
    h = *(uint32_t*)&hh;
    l = *(uint32_t*)&ll;
}

extern "C" __global__ void __launch_bounds__(NTH, 1)
hh_hmma_kernel(const float* __restrict__ z, const float* __restrict__ v,
               const float* __restrict__ W, const float* __restrict__ b,
               float* __restrict__ out, int B)
{
    extern __shared__ char sm[];
    float* zs  = (float*)(sm + ZS_OFF);
    float* psd = (float*)(sm + PSD_OFF);
    float* psn = (float*)(sm + PSN_OFF);
    float* scs = (float*)(sm + SC_OFF);

    const int tid  = threadIdx.x;
    const int w    = tid >> 5;
    const int lane = tid & 31;
    const int cg   = w & 3;          // column group (32 cols)
    const int rg   = w >> 2;         // row group (64 rows)
    const int n0   = cg * 32;
    const int qk   = (lane & 3) * 2;
    const int qr   = lane >> 2;

    const uint32_t sm_u  = s2u(sm);
    const uint32_t zs_u  = sm_u + ZS_OFF;
    const uint32_t ahib  = sm_u + A_HI_OFF
                         + (uint32_t)(rg * 64 + (lane & 15)) * A_STRIDE
                         + (uint32_t)(lane >> 4) * 16;
    const uint32_t alob  = ahib + (uint32_t)(A_LO_OFF - A_HI_OFF);
    // W_lo ldmatrix bases (x4: matrices {n0..+7,k0-7},{..,k8-15},{n0+8..,k0-7},{..,k8-15})
    const int mi   = lane >> 3;
    const int r8   = lane & 7;
    const uint32_t wlob0 = sm_u + WLO_OFF
                         + (uint32_t)(n0 + (mi >> 1) * 8 + r8) * A_STRIDE
                         + (uint32_t)(mi & 1) * 16;
    const uint32_t wlob1 = wlob0 + 16u * A_STRIDE;   // cols n0+16..n0+31

    // ---- one-time: W_hi fragments in regs; W_lo rows into smem; bias ----
    uint32_t bh[4][8][2];
    #pragma unroll
    for (int nt = 0; nt < 4; nt++) {
        const int n = n0 + nt * 8 + qr;
        #pragma unroll
        for (int kk = 0; kk < 8; kk++) {
            uint32_t l0d, l1d;
            float2 x0 = *(const float2*)&W[n * DDIM + kk * 16 + qk];
            float2 x1 = *(const float2*)&W[n * DDIM + kk * 16 + qk + 8];
            split2(x0, bh[nt][kk][0], l0d);
            split2(x1, bh[nt][kk][1], l1d);
        }
    }
    #pragma unroll
    for (int it = 0; it < 32; it++) {
        int p   = tid + it * NTH;         // pair index over 128x64
        int row = p >> 6;
        int kp  = p & 63;
        float2 x = *(const float2*)&W[row * DDIM + kp * 2];
        uint32_t h, l;
        split2(x, h, l);
        *(uint32_t*)(sm + WLO_OFF + row * A_STRIDE + kp * 4) = l;
    }
    float2 bias[4];
    #pragma unroll
    for (int nt = 0; nt < 4; nt++) bias[nt] = *(const float2*)&b[n0 + nt * 8 + qk];
    __syncthreads();

    const int ntiles = B / TILE_M;

    // ---- prologue: v(t0) into registers, two halves ----
    float4 vrega[8], vregb[8];   // rows 0-63, rows 64-127
    {
        int t0 = blockIdx.x;
        if (t0 < ntiles) {
            const float* src = v + (size_t)t0 * TILE_M * DDIM;
            #pragma unroll
            for (int j = 0; j < 8; j++) {
                int c = tid + j * NTH;                     // float4 idx in half
                vrega[j] = *(const float4*)(src + (size_t)c * 4);
                vregb[j] = *(const float4*)(src + (size_t)(c + 2048) * 4);
            }
        }
    }

    for (int tile = blockIdx.x; tile < ntiles; tile += gridDim.x) {
        const size_t tb = (size_t)tile * TILE_M * DDIM;
        const int nxt = tile + (int)gridDim.x;

        // ---- z prefetch for this tile ----
        {
            const float* src = z + tb;
            #pragma unroll
            for (int j = 0; j < 16; j++) {
                int c  = tid + j * NTH;
                int r4 = c >> 5, c4 = c & 31;
                cpa16(zs_u + (uint32_t)(r4 * (ZS_FSTRIDE * 4) + c4 * 16), src + (size_t)c * 4);
            }
            cpa_commit();
        }

        // ---- convert v regs -> A hi/lo smem ----
        #pragma unroll
        for (int j = 0; j < 8; j++) {
            int c   = tid + j * NTH;
            int row = c >> 5;
            int k   = (c & 31) * 4;
            uint32_t h0, l0, h1, l1;
            split2(make_float2(vrega[j].x, vrega[j].y), h0, l0);
            split2(make_float2(vrega[j].z, vrega[j].w), h1, l1);
            *(uint2*)(sm + A_HI_OFF + row * A_STRIDE + k * 2) = make_uint2(h0, h1);
            *(uint2*)(sm + A_LO_OFF + row * A_STRIDE + k * 2) = make_uint2(l0, l1);
            split2(make_float2(vregb[j].x, vregb[j].y), h0, l0);
            split2(make_float2(vregb[j].z, vregb[j].w), h1, l1);
            *(uint2*)(sm + A_HI_OFF + (row + 64) * A_STRIDE + k * 2) = make_uint2(h0, h1);
            *(uint2*)(sm + A_LO_OFF + (row + 64) * A_STRIDE + k * 2) = make_uint2(l0, l1);
        }
        __syncthreads();

        // ---- issue v(next) first half; flies under the MMA phase ----
        if (nxt < ntiles) {
            const float* src = v + (size_t)nxt * TILE_M * DDIM;
            #pragma unroll
            for (int j = 0; j < 8; j++) {
                int c = tid + j * NTH;
                vrega[j] = *(const float4*)(src + (size_t)c * 4);
            }
        }

        // ---- MMA: 3-pass split bf16 (hi*hi + hi*lo + lo*hi) ----
        float acc[4][4][4];
        #pragma unroll
        for (int mt = 0; mt < 4; mt++)
            #pragma unroll
            for (int nt = 0; nt < 4; nt++)
                #pragma unroll
                for (int i = 0; i < 4; i++) acc[mt][nt][i] = 0.f;

        #pragma unroll
        for (int kk = 0; kk < 8; kk++) {
            uint32_t blf[8];
            ldmx4(blf[0], blf[1], blf[2], blf[3], wlob0 + (uint32_t)kk * 32);
            ldmx4(blf[4], blf[5], blf[6], blf[7], wlob1 + (uint32_t)kk * 32);
            #pragma unroll
            for (int mt = 0; mt < 4; mt++) {
                uint32_t ah0, ah1, ah2, ah3, al0, al1, al2, al3;
                const uint32_t off = (uint32_t)mt * (16 * A_STRIDE) + (uint32_t)kk * 32;
                ldmx4(ah0, ah1, ah2, ah3, ahib + off);
                ldmx4(al0, al1, al2, al3, alob + off);
                #pragma unroll
                for (int nt = 0; nt < 4; nt++) {
                    mma_bf16(acc[mt][nt][0], acc[mt][nt][1], acc[mt][nt][2], acc[mt][nt][3],
                             ah0, ah1, ah2, ah3, bh[nt][kk][0], bh[nt][kk][1]);
                    mma_bf16(acc[mt][nt][0], acc[mt][nt][1], acc[mt][nt][2], acc[mt][nt][3],
                             ah0, ah1, ah2, ah3, blf[nt * 2], blf[nt * 2 + 1]);
                    mma_bf16(acc[mt][nt][0], acc[mt][nt][1], acc[mt][nt][2], acc[mt][nt][3],
                             al0, al1, al2, al3, bh[nt][kk][0], bh[nt][kk][1]);
                }
            }
        }

        // ---- z ready; second v(next) half flies under the epilogue ----
        cpa_wait0();
        __syncthreads();
        if (nxt < ntiles) {
            const float* src = v + (size_t)nxt * TILE_M * DDIM;
            #pragma unroll
            for (int j = 0; j < 8; j++) {
                int c = tid + j * NTH;
                vregb[j] = *(const float4*)(src + (size_t)(c + 2048) * 4);
            }
        }

        // ---- partial dot/norm per row ----
        #pragma unroll
        for (int mt = 0; mt < 4; mt++) {
            const int rt = rg * 64 + mt * 16 + qr;
            const float* zr0 = &zs[rt * ZS_FSTRIDE];
            const float* zr1 = zr0 + 8 * ZS_FSTRIDE;
            float d0 = 0.f, m0 = 0.f, d1 = 0.f, m1 = 0.f;
            #pragma unroll
            for (int nt = 0; nt < 4; nt++) {
                float2 za = *(const float2*)&zr0[n0 + nt * 8 + qk];
                float2 zb = *(const float2*)&zr1[n0 + nt * 8 + qk];
                float vn0 = acc[mt][nt][0] + bias[nt].x;
                float vn1 = acc[mt][nt][1] + bias[nt].y;
                float vn2 = acc[mt][nt][2] + bias[nt].x;
                float vn3 = acc[mt][nt][3] + bias[nt].y;
                d0 = fmaf(vn0, za.x, d0); d0 = fmaf(vn1, za.y, d0);
                m0 = fmaf(vn0, vn0, m0);  m0 = fmaf(vn1, vn1, m0);
                d1 = fmaf(vn2, zb.x, d1); d1 = fmaf(vn3, zb.y, d1);
                m1 = fmaf(vn2, vn2, m1);  m1 = fmaf(vn3, vn3, m1);
            }
            d0 += __shfl_xor_sync(0xffffffffu, d0, 1);
            d0 += __shfl_xor_sync(0xffffffffu, d0, 2);
            m0 += __shfl_xor_sync(0xffffffffu, m0, 1);
            m0 += __shfl_xor_sync(0xffffffffu, m0, 2);
            d1 += __shfl_xor_sync(0xffffffffu, d1, 1);
            d1 += __shfl_xor_sync(0xffffffffu, d1, 2);
            m1 += __shfl_xor_sync(0xffffffffu, m1, 1);
            m1 += __shfl_xor_sync(0xffffffffu, m1, 2);
            if ((lane & 3) == 0) {
                psd[cg * TILE_M + rt]     = d0;
                psd[cg * TILE_M + rt + 8] = d1;
                psn[cg * TILE_M + rt]     = m0;
                psn[cg * TILE_M + rt + 8] = m1;
            }
        }
        __syncthreads();

        if (tid < TILE_M) {
            float dt = psd[tid] + psd[TILE_M + tid] + psd[2 * TILE_M + tid] + psd[3 * TILE_M + tid];
            float nm = psn[tid] + psn[TILE_M + tid] + psn[2 * TILE_M + tid] + psn[3 * TILE_M + tid];
            scs[tid] = 2.0f * dt / nm;
        }
        __syncthreads();

        // ---- reflect + store ----
        #pragma unroll
        for (int mt = 0; mt < 4; mt++) {
            const int rt = rg * 64 + mt * 16 + qr;
            const float s0 = scs[rt];
            const float s1 = scs[rt + 8];
            const float* zr0 = &zs[rt * ZS_FSTRIDE];
            const float* zr1 = zr0 + 8 * ZS_FSTRIDE;
            float* or0 = out + tb + (size_t)rt * DDIM;
            float* or1 = or0 + 8 * DDIM;
            #pragma unroll
            for (int nt = 0; nt < 4; nt++) {
                float2 za = *(const float2*)&zr0[n0 + nt * 8 + qk];
                float2 zb = *(const float2*)&zr1[n0 + nt * 8 + qk];
                float2 o;
                o.x = za.x - s0 * (acc[mt][nt][0] + bias[nt].x);
                o.y = za.y - s0 * (acc[mt][nt][1] + bias[nt].y);
                *(float2*)&or0[n0 + nt * 8 + qk] = o;
                o.x = zb.x - s1 * (acc[mt][nt][2] + bias[nt].x);
                o.y = zb.y - s1 * (acc[mt][nt][3] + bias[nt].y);
                *(float2*)&or1[n0 + nt * 8 + qk] = o;
            }
        }
        __syncthreads();   // protect zs / A / psd before next tile's writers
    }
}

extern "C" void kernel_launch(void* const* d_in, const int* in_sizes, int n_in,
                              void* d_out, int out_size) {
    const float* z = (const float*)d_in[0];
    const float* v = (const float*)d_in[1];
    const float* W = (const float*)d_in[2];
    const float* b = (const float*)d_in[3];
    float* out = (float*)d_out;

    const int B = in_sizes[0] / DDIM;

    cudaFuncSetAttribute(hh_hmma_kernel, cudaFuncAttributeMaxDynamicSharedMemorySize, SMEM_TOTAL);
    hh_hmma_kernel<<<148, NTH, SMEM_TOTAL>>>(z, v, W, b, out, B);
}

// round 8
// speedup vs baseline: 1.0370x; 1.0370x over previous
#include <cuda_runtime.h>
#include <cuda_bf16.h>
#include <cstdint>

#define DDIM   128
#define TILE_M 128
#define NTH    512
#define NWARP  16

// ---- smem layout (bytes) ----
#define A_STRIDE 272                          // bf16 row: 256 data + 16 pad
#define A_HI_OFF 0
#define A_LO_OFF (TILE_M * A_STRIDE)          // 34816
#define W_HI_OFF (2 * TILE_M * A_STRIDE)      // 69632
#define W_LO_OFF (3 * TILE_M * A_STRIDE)      // 104448
#define ZS_OFF   (4 * TILE_M * A_STRIDE)      // 139264
#define ZS_FSTRIDE 132
#define ZS_SZ    (TILE_M * ZS_FSTRIDE * 4)    // 67584
#define PSD_OFF  (ZS_OFF + ZS_SZ)             // 206848  [4][128] floats
#define PSN_OFF  (PSD_OFF + 4 * TILE_M * 4)
#define SC_OFF   (PSN_OFF + 4 * TILE_M * 4)
#define SMEM_TOTAL (SC_OFF + TILE_M * 4)      // 211456

__device__ __forceinline__ uint32_t s2u(const void* p) {
    return (uint32_t)__cvta_generic_to_shared(p);
}
__device__ __forceinline__ void cpa16(uint32_t dst, const void* src) {
    asm volatile("cp.async.cg.shared.global [%0], [%1], 16;" :: "r"(dst), "l"(src) : "memory");
}
__device__ __forceinline__ void cpa_commit() {
    asm volatile("cp.async.commit_group;" ::: "memory");
}
__device__ __forceinline__ void cpa_wait0() {
    asm volatile("cp.async.wait_group 0;" ::: "memory");
}
__device__ __forceinline__ void mma_bf16(float& d0, float& d1, float& d2, float& d3,
                                         uint32_t a0, uint32_t a1, uint32_t a2, uint32_t a3,
                                         uint32_t b0, uint32_t b1) {
    asm volatile("mma.sync.aligned.m16n8k16.row.col.f32.bf16.bf16.f32 "
                 "{%0,%1,%2,%3}, {%4,%5,%6,%7}, {%8,%9}, {%0,%1,%2,%3};"
                 : "+f"(d0), "+f"(d1), "+f"(d2), "+f"(d3)
                 : "r"(a0), "r"(a1), "r"(a2), "r"(a3), "r"(b0), "r"(b1));
}
__device__ __forceinline__ void ldmx4(uint32_t& r0, uint32_t& r1, uint32_t& r2, uint32_t& r3,
                                      uint32_t addr) {
    asm volatile("ldmatrix.sync.aligned.m8n8.x4.shared.b16 {%0,%1,%2,%3}, [%4];"
                 : "=r"(r0), "=r"(r1), "=r"(r2), "=r"(r3) : "r"(addr));
}
__device__ __forceinline__ void split2(float2 x, uint32_t& h, uint32_t& l) {
    __nv_bfloat16 h0 = __float2bfloat16_rn(x.x);
    __nv_bfloat16 h1 = __float2bfloat16_rn(x.y);
    __nv_bfloat16 l0 = __float2bfloat16_rn(x.x - __bfloat162float(h0));
    __nv_bfloat16 l1 = __float2bfloat16_rn(x.y - __bfloat162float(h1));
    __nv_bfloat162 hh = __halves2bfloat162(h0, h1);
    __nv_bfloat162 ll = __halves2bfloat162(l0, l1);
    h = *(uint32_t*)&hh;
    l = *(uint32_t*)&ll;
}

extern "C" __global__ void __launch_bounds__(NTH, 1)
hh_hmma_kernel(const float* __restrict__ z, const float* __restrict__ v,
               const float* __restrict__ W, const float* __restrict__ b,
               float* __restrict__ out, int B)
{
    extern __shared__ char sm[];
    float* zs  = (float*)(sm + ZS_OFF);
    float* psd = (float*)(sm + PSD_OFF);
    float* psn = (float*)(sm + PSN_OFF);
    float* scs = (float*)(sm + SC_OFF);

    const int tid  = threadIdx.x;
    const int w    = tid >> 5;
    const int lane = tid & 31;
    const int cg   = w & 3;          // column group (32 cols)
    const int rg   = w >> 2;         // row group (32 rows)
    const int n0   = cg * 32;
    const int qk   = (lane & 3) * 2;
    const int qr   = lane >> 2;

    const uint32_t sm_u = s2u(sm);
    const uint32_t zs_u = sm_u + ZS_OFF;
    const uint32_t ahib = sm_u + A_HI_OFF
                        + (uint32_t)(rg * 32 + (lane & 15)) * A_STRIDE
                        + (uint32_t)(lane >> 4) * 16;
    const uint32_t alob = ahib + (uint32_t)(A_LO_OFF - A_HI_OFF);
    // W ldmatrix bases: x4 -> {n..n+7,k0-7},{n..n+7,k8-15},{n+8..15,k0-7},{n+8..15,k8-15}
    const int mi = lane >> 3;
    const int r8 = lane & 7;
    const uint32_t whib0 = sm_u + W_HI_OFF
                         + (uint32_t)(n0 + (mi >> 1) * 8 + r8) * A_STRIDE
                         + (uint32_t)(mi & 1) * 16;
    const uint32_t whib1 = whib0 + 16u * A_STRIDE;
    const uint32_t wlob0 = whib0 + (uint32_t)(W_LO_OFF - W_HI_OFF);
    const uint32_t wlob1 = whib1 + (uint32_t)(W_LO_OFF - W_HI_OFF);

    // ---- one-time: W -> hi/lo smem tiles; bias ----
    #pragma unroll
    for (int it = 0; it < 16; it++) {
        int p   = tid + it * NTH;         // pair index over 128x64
        int row = p >> 6;
        int kp  = p & 63;
        float2 x = *(const float2*)&W[row * DDIM + kp * 2];
        uint32_t h, l;
        split2(x, h, l);
        *(uint32_t*)(sm + W_HI_OFF + row * A_STRIDE + kp * 4) = h;
        *(uint32_t*)(sm + W_LO_OFF + row * A_STRIDE + kp * 4) = l;
    }
    float2 bias[4];
    #pragma unroll
    for (int nt = 0; nt < 4; nt++) bias[nt] = *(const float2*)&b[n0 + nt * 8 + qk];
    __syncthreads();

    const int ntiles = B / TILE_M;

    // ---- prologue: v(t0) into registers, two halves ----
    float4 vrega[4], vregb[4];   // rows 0-63, rows 64-127
    {
        int t0 = blockIdx.x;
        if (t0 < ntiles) {
            const float* src = v + (size_t)t0 * TILE_M * DDIM;
            #pragma unroll
            for (int j = 0; j < 4; j++) {
                int c = tid + j * NTH;                     // float4 idx in half
                vrega[j] = *(const float4*)(src + (size_t)c * 4);
                vregb[j] = *(const float4*)(src + (size_t)(c + 2048) * 4);
            }
        }
    }

    for (int tile = blockIdx.x; tile < ntiles; tile += gridDim.x) {
        const size_t tb = (size_t)tile * TILE_M * DDIM;
        const int nxt = tile + (int)gridDim.x;

        // ---- z prefetch for this tile ----
        {
            const float* src = z + tb;
            #pragma unroll
            for (int j = 0; j < 8; j++) {
                int c  = tid + j * NTH;
                int r4 = c >> 5, c4 = c & 31;
                cpa16(zs_u + (uint32_t)(r4 * (ZS_FSTRIDE * 4) + c4 * 16), src + (size_t)c * 4);
            }
            cpa_commit();
        }

        // ---- convert v regs -> A hi/lo smem ----
        #pragma unroll
        for (int j = 0; j < 4; j++) {
            int c   = tid + j * NTH;
            int row = c >> 5;
            int k   = (c & 31) * 4;
            uint32_t h0, l0, h1, l1;
            split2(make_float2(vrega[j].x, vrega[j].y), h0, l0);
            split2(make_float2(vrega[j].z, vrega[j].w), h1, l1);
            *(uint2*)(sm + A_HI_OFF + row * A_STRIDE + k * 2) = make_uint2(h0, h1);
            *(uint2*)(sm + A_LO_OFF + row * A_STRIDE + k * 2) = make_uint2(l0, l1);
            split2(make_float2(vregb[j].x, vregb[j].y), h0, l0);
            split2(make_float2(vregb[j].z, vregb[j].w), h1, l1);
            *(uint2*)(sm + A_HI_OFF + (row + 64) * A_STRIDE + k * 2) = make_uint2(h0, h1);
            *(uint2*)(sm + A_LO_OFF + (row + 64) * A_STRIDE + k * 2) = make_uint2(l0, l1);
        }
        __syncthreads();

        // ---- issue v(next) first half; flies under the MMA phase ----
        if (nxt < ntiles) {
            const float* src = v + (size_t)nxt * TILE_M * DDIM;
            #pragma unroll
            for (int j = 0; j < 4; j++) {
                int c = tid + j * NTH;
                vrega[j] = *(const float4*)(src + (size_t)c * 4);
            }
        }

        // ---- MMA: 3-pass split bf16 (hi*hi + hi*lo + lo*hi) ----
        float acc[2][4][4];
        #pragma unroll
        for (int mt = 0; mt < 2; mt++)
            #pragma unroll
            for (int nt = 0; nt < 4; nt++)
                #pragma unroll
                for (int i = 0; i < 4; i++) acc[mt][nt][i] = 0.f;

        #pragma unroll
        for (int kk = 0; kk < 8; kk++) {
            uint32_t bhf[8], blf[8];
            ldmx4(bhf[0], bhf[1], bhf[2], bhf[3], whib0 + (uint32_t)kk * 32);
            ldmx4(bhf[4], bhf[5], bhf[6], bhf[7], whib1 + (uint32_t)kk * 32);
            ldmx4(blf[0], blf[1], blf[2], blf[3], wlob0 + (uint32_t)kk * 32);
            ldmx4(blf[4], blf[5], blf[6], blf[7], wlob1 + (uint32_t)kk * 32);
            #pragma unroll
            for (int mt = 0; mt < 2; mt++) {
                uint32_t ah0, ah1, ah2, ah3, al0, al1, al2, al3;
                const uint32_t off = (uint32_t)mt * (16 * A_STRIDE) + (uint32_t)kk * 32;
                ldmx4(ah0, ah1, ah2, ah3, ahib + off);
                ldmx4(al0, al1, al2, al3, alob + off);
                #pragma unroll
                for (int nt = 0; nt < 4; nt++) {
                    mma_bf16(acc[mt][nt][0], acc[mt][nt][1], acc[mt][nt][2], acc[mt][nt][3],
                             ah0, ah1, ah2, ah3, bhf[nt * 2], bhf[nt * 2 + 1]);
                    mma_bf16(acc[mt][nt][0], acc[mt][nt][1], acc[mt][nt][2], acc[mt][nt][3],
                             ah0, ah1, ah2, ah3, blf[nt * 2], blf[nt * 2 + 1]);
                    mma_bf16(acc[mt][nt][0], acc[mt][nt][1], acc[mt][nt][2], acc[mt][nt][3],
                             al0, al1, al2, al3, bhf[nt * 2], bhf[nt * 2 + 1]);
                }
            }
        }

        // ---- z ready; second v(next) half flies under the epilogue ----
        cpa_wait0();
        __syncthreads();
        if (nxt < ntiles) {
            const float* src = v + (size_t)nxt * TILE_M * DDIM;
            #pragma unroll
            for (int j = 0; j < 4; j++) {
                int c = tid + j * NTH;
                vregb[j] = *(const float4*)(src + (size_t)(c + 2048) * 4);
            }
        }

        // ---- partial dot/norm per row ----
        #pragma unroll
        for (int mt = 0; mt < 2; mt++) {
            const int rt = rg * 32 + mt * 16 + qr;
            const float* zr0 = &zs[rt * ZS_FSTRIDE];
            const float* zr1 = zr0 + 8 * ZS_FSTRIDE;
            float d0 = 0.f, m0 = 0.f, d1 = 0.f, m1 = 0.f;
            #pragma unroll
            for (int nt = 0; nt < 4; nt++) {
                float2 za = *(const float2*)&zr0[n0 + nt * 8 + qk];
                float2 zb = *(const float2*)&zr1[n0 + nt * 8 + qk];
                float vn0 = acc[mt][nt][0] + bias[nt].x;
                float vn1 = acc[mt][nt][1] + bias[nt].y;
                float vn2 = acc[mt][nt][2] + bias[nt].x;
                float vn3 = acc[mt][nt][3] + bias[nt].y;
                d0 = fmaf(vn0, za.x, d0); d0 = fmaf(vn1, za.y, d0);
                m0 = fmaf(vn0, vn0, m0);  m0 = fmaf(vn1, vn1, m0);
                d1 = fmaf(vn2, zb.x, d1); d1 = fmaf(vn3, zb.y, d1);
                m1 = fmaf(vn2, vn2, m1);  m1 = fmaf(vn3, vn3, m1);
            }
            d0 += __shfl_xor_sync(0xffffffffu, d0, 1);
            d0 += __shfl_xor_sync(0xffffffffu, d0, 2);
            m0 += __shfl_xor_sync(0xffffffffu, m0, 1);
            m0 += __shfl_xor_sync(0xffffffffu, m0, 2);
            d1 += __shfl_xor_sync(0xffffffffu, d1, 1);
            d1 += __shfl_xor_sync(0xffffffffu, d1, 2);
            m1 += __shfl_xor_sync(0xffffffffu, m1, 1);
            m1 += __shfl_xor_sync(0xffffffffu, m1, 2);
            if ((lane & 3) == 0) {
                psd[cg * TILE_M + rt]     = d0;
                psd[cg * TILE_M + rt + 8] = d1;
                psn[cg * TILE_M + rt]     = m0;
                psn[cg * TILE_M + rt + 8] = m1;
            }
        }
        __syncthreads();

        if (tid < TILE_M) {
            float dt = psd[tid] + psd[TILE_M + tid] + psd[2 * TILE_M + tid] + psd[3 * TILE_M + tid];
            float nm = psn[tid] + psn[TILE_M + tid] + psn[2 * TILE_M + tid] + psn[3 * TILE_M + tid];
            scs[tid] = 2.0f * dt / nm;
        }
        __syncthreads();

        // ---- reflect + store ----
        #pragma unroll
        for (int mt = 0; mt < 2; mt++) {
            const int rt = rg * 32 + mt * 16 + qr;
            const float s0 = scs[rt];
            const float s1 = scs[rt + 8];
            const float* zr0 = &zs[rt * ZS_FSTRIDE];
            const float* zr1 = zr0 + 8 * ZS_FSTRIDE;
            float* or0 = out + tb + (size_t)rt * DDIM;
            float* or1 = or0 + 8 * DDIM;
            #pragma unroll
            for (int nt = 0; nt < 4; nt++) {
                float2 za = *(const float2*)&zr0[n0 + nt * 8 + qk];
                float2 zb = *(const float2*)&zr1[n0 + nt * 8 + qk];
                float2 o;
                o.x = za.x - s0 * (acc[mt][nt][0] + bias[nt].x);
                o.y = za.y - s0 * (acc[mt][nt][1] + bias[nt].y);
                *(float2*)&or0[n0 + nt * 8 + qk] = o;
                o.x = zb.x - s1 * (acc[mt][nt][2] + bias[nt].x);
                o.y = zb.y - s1 * (acc[mt][nt][3] + bias[nt].y);
                *(float2*)&or1[n0 + nt * 8 + qk] = o;
            }
        }
        __syncthreads();   // protect zs / A / psd before next tile's writers
    }
}

extern "C" void kernel_launch(void* const* d_in, const int* in_sizes, int n_in,
                              void* d_out, int out_size) {
    const float* z = (const float*)d_in[0];
    const float* v = (const float*)d_in[1];
    const float* W = (const float*)d_in[2];
    const float* b = (const float*)d_in[3];
    float* out = (float*)d_out;

    const int B = in_sizes[0] / DDIM;

    cudaFuncSetAttribute(hh_hmma_kernel, cudaFuncAttributeMaxDynamicSharedMemorySize, SMEM_TOTAL);
    hh_hmma_kernel<<<148, NTH, SMEM_TOTAL>>>(z, v, W, b, out, B);
}